// round 12
// baseline (speedup 1.0000x reference)
#include <cuda_runtime.h>

// Problem constants (from reference setup_inputs)
#define BD   8        // batch
#define NN   2048     // N = O*K
#define HH   128      // hidden
#define TT   10       // pred_len
#define MAXN 256      // neighbor cap (avg degree ~10)

// ---------------- device scratch (no allocations allowed) ----------------
__device__ float g_pos[BD * NN * 3];
__device__ float g_vel[BD * NN * 3];
__device__ __align__(16) float g_ha[BD * NN * HH];     // h ping
__device__ __align__(16) float g_hb[BD * NN * HH];     // h pong
__device__ int   g_nbr[BD * NN * MAXN];
__device__ int   g_cnt[BD * NN];
__device__ float g_dinv[BD * NN];

// ---------------- init: pos=points, vel=0, write t=0 output ----------------
__global__ void k_init(const float* __restrict__ pts, float* __restrict__ out) {
    int id = blockIdx.x * blockDim.x + threadIdx.x;   // over B*N*3
    if (id < BD * NN * 3) {
        float v = pts[id];
        g_pos[id] = v;
        g_vel[id] = 0.f;
        int c = id % 3;
        int n = (id / 3) % NN;
        int b = id / (3 * NN);
        out[((size_t)(b * (TT + 1)) * NN + n) * 3 + c] = v;
    }
}

// ---------------- adjacency + fused layer0 h --------------------------------
// grid (NN/64, BD), 256 threads.
__global__ __launch_bounds__(256) void k_adj(const float* __restrict__ padding,
                                             const float* __restrict__ W0) {
    __shared__ float px[NN], py[NN], pz[NN], pd[NN];
    __shared__ float W0s[6 * HH];
    __shared__ float sv[64][3];
    __shared__ float sdinv[64];
    int b = blockIdx.y, bN = b * NN;
    int i0 = blockIdx.x * 64;
    int tid = threadIdx.x;
    const float* pos = g_pos + (size_t)bN * 3;
    for (int j = tid; j < NN; j += 256) {
        px[j] = pos[j * 3 + 0];
        py[j] = pos[j * 3 + 1];
        pz[j] = pos[j * 3 + 2];
        pd[j] = padding[bN + j];
    }
    for (int k = tid; k < 6 * HH; k += 256) W0s[k] = W0[k];
    if (tid < 192) sv[tid / 3][tid % 3] = g_vel[(bN + i0 + tid / 3) * 3 + tid % 3];
    __syncthreads();

    int warp = tid >> 5, lane = tid & 31;
    const float R2 = 0.01f;   // float32(0.1*0.1), fp32 compare like the ref
    for (int r = 0; r < 8; r++) {
        int rr = r * 8 + warp;            // row-in-block 0..63
        int i = i0 + rr;
        float xi = px[i], yi = py[i], zi = pz[i];
        bool oki = pd[i] > 0.f;
        int base = (bN + i) * MAXN;
        int cnt = 0;
        #pragma unroll 4
        for (int t = 0; t < NN / 32; t++) {
            int j = t * 32 + lane;
            // separate mul/add rounding — matches XLA's sub/mul/reduce-add
            float dx = __fadd_rn(px[j], -xi);
            float dy = __fadd_rn(py[j], -yi);
            float dz = __fadd_rn(pz[j], -zi);
            float d2 = __fadd_rn(__fadd_rn(__fmul_rn(dx, dx), __fmul_rn(dy, dy)),
                                 __fmul_rn(dz, dz));
            // a_hat = adj + I: diagonal always 1; self at its sorted position
            bool hit = (j == i) || (oki && (pd[j] > 0.f) && (d2 < R2));
            unsigned m = __ballot_sync(0xffffffffu, hit);
            if (hit) {
                int off = cnt + __popc(m & ((1u << lane) - 1u));
                if (off < MAXN) g_nbr[base + off] = j;
            }
            cnt += __popc(m);
        }
        if (cnt > MAXN) cnt = MAXN;
        if (lane == 0) {
            // XLA lowers rsqrt as 1/sqrt (correctly rounded), NOT MUFU.RSQ.
            float di = 1.0f / sqrtf((float)cnt);
            g_cnt[bN + i]  = cnt;
            g_dinv[bN + i] = di;
            sdinv[rr] = di;
        }
    }
    __syncthreads();

    // layer0 h for own rows (ascending-k FMA, pos then vel)
    for (int o = tid; o < 64 * HH; o += 256) {
        int r = o >> 7, col = o & 127;
        float acc = 0.f;
        acc = fmaf(px[i0 + r], W0s[0 * HH + col], acc);
        acc = fmaf(py[i0 + r], W0s[1 * HH + col], acc);
        acc = fmaf(pz[i0 + r], W0s[2 * HH + col], acc);
        acc = fmaf(sv[r][0],   W0s[3 * HH + col], acc);
        acc = fmaf(sv[r][1],   W0s[4 * HH + col], acc);
        acc = fmaf(sv[r][2],   W0s[5 * HH + col], acc);
        g_ha[(size_t)(bN + i0 + r) * HH + col] = __fmul_rn(acc, sdinv[r]);
    }
}

// MLP-4 gather: 4 independent LDG.128 in flight, then ordered adds
// (strictly ascending t — bit-identical to the serial loop).
__device__ __forceinline__ float4 gather_row(const float* __restrict__ hin,
                                             const int* __restrict__ nb,
                                             int cnt, int bN, int lane) {
    float4 a = make_float4(0.f, 0.f, 0.f, 0.f);
    int t = 0;
    for (; t + 4 <= cnt; t += 4) {
        int j0 = nb[t], j1 = nb[t + 1], j2 = nb[t + 2], j3 = nb[t + 3];
        float4 v0 = __ldg((const float4*)(hin + (size_t)(bN + j0) * HH) + lane);
        float4 v1 = __ldg((const float4*)(hin + (size_t)(bN + j1) * HH) + lane);
        float4 v2 = __ldg((const float4*)(hin + (size_t)(bN + j2) * HH) + lane);
        float4 v3 = __ldg((const float4*)(hin + (size_t)(bN + j3) * HH) + lane);
        a.x = __fadd_rn(a.x, v0.x); a.y = __fadd_rn(a.y, v0.y);
        a.z = __fadd_rn(a.z, v0.z); a.w = __fadd_rn(a.w, v0.w);
        a.x = __fadd_rn(a.x, v1.x); a.y = __fadd_rn(a.y, v1.y);
        a.z = __fadd_rn(a.z, v1.z); a.w = __fadd_rn(a.w, v1.w);
        a.x = __fadd_rn(a.x, v2.x); a.y = __fadd_rn(a.y, v2.y);
        a.z = __fadd_rn(a.z, v2.z); a.w = __fadd_rn(a.w, v2.w);
        a.x = __fadd_rn(a.x, v3.x); a.y = __fadd_rn(a.y, v3.y);
        a.z = __fadd_rn(a.z, v3.z); a.w = __fadd_rn(a.w, v3.w);
    }
    for (; t < cnt; t++) {
        float4 v = __ldg((const float4*)(hin + (size_t)(bN + nb[t]) * HH) + lane);
        a.x = __fadd_rn(a.x, v.x); a.y = __fadd_rn(a.y, v.y);
        a.z = __fadd_rn(a.z, v.z); a.w = __fadd_rn(a.w, v.w);
    }
    return a;
}

// ---------------- fused aggregate + dense GEMM, shuffle-based ---------------
// Warp w owns rows 8w..8w+7. Gathered x stays in registers (lane holds cols
// 4*lane..4*lane+3 of each row); GEMM broadcasts x[r][k] via __shfl_sync.
// No xs smem -> 65KB/CTA -> 3 CTAs/SM.
// src==0: g_ha -> g_hb ; src==1: g_hb -> g_ha.
__global__ __launch_bounds__(256, 3) void k_aggemm(int src,
                                                   const float* __restrict__ bias,
                                                   const float* __restrict__ W) {
    extern __shared__ __align__(16) float sm[];
    float* Ws = sm;                 // 128*128
    float* dj = sm + HH * HH;       // 64
    float* bs = dj + 64;            // 128

    const float* hin  = src ? g_hb : g_ha;
    float*       hout = src ? g_ha : g_hb;

    int row0 = blockIdx.x * 64;
    int tid = threadIdx.x;
    int bN = (row0 / NN) * NN;       // neighbors are batch-local ids

    for (int k = tid; k < HH * HH; k += 256) Ws[k] = W[k];
    if (tid < HH) bs[tid] = bias[tid];
    if (tid < 64) dj[tid] = g_dinv[row0 + tid];
    __syncthreads();                 // only sync: W/bias/dinv visible

    int warp = tid >> 5, lane = tid & 31;
    int rbase = warp * 8;

    // Phase A (warp-local): gather own 8 rows; results stay in registers.
    float4 xv[8];
    float4 bb = ((const float4*)bs)[lane];
    #pragma unroll 1
    for (int rr = 0; rr < 8; rr++) {
        int i = row0 + rbase + rr;
        float4 a = gather_row(hin, g_nbr + (size_t)i * MAXN, g_cnt[i], bN, lane);
        float di = dj[rbase + rr];
        xv[rr].x = fmaxf(__fadd_rn(__fmul_rn(a.x, di), bb.x), 0.f);
        xv[rr].y = fmaxf(__fadd_rn(__fmul_rn(a.y, di), bb.y), 0.f);
        xv[rr].z = fmaxf(__fadd_rn(__fmul_rn(a.z, di), bb.z), 0.f);
        xv[rr].w = fmaxf(__fadd_rn(__fmul_rn(a.w, di), bb.w), 0.f);
    }

    // Phase B: acc[r][c] = sum_k x[r][k] * W[k][c], k strictly ascending.
    // x[r][k] lives in lane k/4, component k%4 -> shfl broadcast.
    float acc[8][4];
    #pragma unroll
    for (int rr = 0; rr < 8; rr++)
        #pragma unroll
        for (int c = 0; c < 4; c++) acc[rr][c] = 0.f;

    #pragma unroll 1
    for (int k0 = 0; k0 < HH; k0 += 4) {
        int srcLane = k0 >> 2;
        #pragma unroll
        for (int kk = 0; kk < 4; kk++) {
            float4 wk = *(const float4*)&Ws[(k0 + kk) * HH + lane * 4];
            #pragma unroll
            for (int rr = 0; rr < 8; rr++) {
                float comp = (kk == 0) ? xv[rr].x : (kk == 1) ? xv[rr].y
                           : (kk == 2) ? xv[rr].z : xv[rr].w;
                float xb = __shfl_sync(0xffffffffu, comp, srcLane);
                acc[rr][0] = fmaf(xb, wk.x, acc[rr][0]);
                acc[rr][1] = fmaf(xb, wk.y, acc[rr][1]);
                acc[rr][2] = fmaf(xb, wk.z, acc[rr][2]);
                acc[rr][3] = fmaf(xb, wk.w, acc[rr][3]);
            }
        }
    }

    #pragma unroll
    for (int rr = 0; rr < 8; rr++) {
        int r = rbase + rr;
        float d = dj[r];
        float4 o;
        o.x = __fmul_rn(acc[rr][0], d);
        o.y = __fmul_rn(acc[rr][1], d);
        o.z = __fmul_rn(acc[rr][2], d);
        o.w = __fmul_rn(acc[rr][3], d);
        *(float4*)&hout[(size_t)(row0 + r) * HH + lane * 4] = o;
    }
}

// ---------------- fused aggregate + fc head + state update, warp-local -----
// Reads g_ha (layer2 gemm output lands there).
__global__ __launch_bounds__(256) void k_aggfc(const float* __restrict__ bias2,
                                               const float* __restrict__ Wfc,
                                               const float* __restrict__ bfc,
                                               const float* __restrict__ padding,
                                               float* __restrict__ out, int t) {
    __shared__ __align__(16) float xs[64 * 132];
    __shared__ float Wf[HH * 6];
    __shared__ float bf[6];
    __shared__ __align__(16) float bs[HH];
    int row0 = blockIdx.x * 64;
    int tid = threadIdx.x;
    int bN = (row0 / NN) * NN;

    for (int k = tid; k < HH * 6; k += 256) Wf[k] = Wfc[k];
    if (tid < 6) bf[tid] = bfc[tid];
    if (tid < HH) bs[tid] = bias2[tid];
    __syncthreads();

    int warp = tid >> 5, lane = tid & 31;
    int rbase = warp * 8;
    #pragma unroll 1
    for (int rr = 0; rr < 8; rr++) {
        int r = rbase + rr;
        int i = row0 + r;
        float4 a = gather_row(g_ha, g_nbr + (size_t)i * MAXN, g_cnt[i], bN, lane);
        float di = g_dinv[i];
        float4 bb = ((const float4*)bs)[lane];
        float4 o;
        o.x = fmaxf(__fadd_rn(__fmul_rn(a.x, di), bb.x), 0.f);
        o.y = fmaxf(__fadd_rn(__fmul_rn(a.y, di), bb.y), 0.f);
        o.z = fmaxf(__fadd_rn(__fmul_rn(a.z, di), bb.z), 0.f);
        o.w = fmaxf(__fadd_rn(__fmul_rn(a.w, di), bb.w), 0.f);
        *(float4*)&xs[r * 132 + lane * 4] = o;
    }
    __syncwarp();

    // fc for own 8 rows: 48 outputs per warp, lanes strided.
    for (int w = lane; w < 8 * 6; w += 32) {
        int rr = w / 6, c = w % 6;
        int g = row0 + rbase + rr;
        const float* xr = xs + (rbase + rr) * 132;
        float acc = 0.f;
        #pragma unroll 8
        for (int k = 0; k < HH; k++) acc = fmaf(xr[k], Wf[k * 6 + c], acc);
        float res = __fadd_rn(acc, bf[c]);
        res = __fmul_rn(res, padding[g]);
        if (c < 3) {
            float p = __fadd_rn(g_pos[g * 3 + c], res);
            g_pos[g * 3 + c] = p;
            int b = g / NN, n = g % NN;
            out[((size_t)(b * (TT + 1) + t + 1) * NN + n) * 3 + c] = p;
        } else {
            int a = g * 3 + (c - 3);
            g_vel[a] = __fadd_rn(g_vel[a], res);
        }
    }
}

// ---------------- launch ----------------
extern "C" void kernel_launch(void* const* d_in, const int* in_sizes, int n_in,
                              void* d_out, int out_size) {
    const float* points  = (const float*)d_in[0];
    const float* padding = (const float*)d_in[5];
    const float* W0  = (const float*)d_in[6];
    const float* b0  = (const float*)d_in[7];
    const float* W1  = (const float*)d_in[8];
    const float* b1  = (const float*)d_in[9];
    const float* W2  = (const float*)d_in[10];
    const float* b2  = (const float*)d_in[11];
    const float* Wfc = (const float*)d_in[12];
    const float* bfc = (const float*)d_in[13];
    float* out = (float*)d_out;

    const int smem_ag = (HH * HH + 64 + HH) * (int)sizeof(float);
    cudaFuncSetAttribute(k_aggemm, cudaFuncAttributeMaxDynamicSharedMemorySize,
                         smem_ag);

    const int ROWS = BD * NN;

    k_init<<<(BD * NN * 3 + 255) / 256, 256>>>(points, out);

    for (int t = 0; t < TT; t++) {
        k_adj<<<dim3(NN / 64, BD), 256>>>(padding, W0);      // -> g_ha (h0)
        k_aggemm<<<ROWS / 64, 256, smem_ag>>>(0, b0, W1);    // ha -> x -> hb
        k_aggemm<<<ROWS / 64, 256, smem_ag>>>(1, b1, W2);    // hb -> x -> ha
        k_aggfc <<<ROWS / 64, 256>>>(b2, Wfc, bfc, padding, out, t);
    }
}

// round 13
// speedup vs baseline: 1.1646x; 1.1646x over previous
#include <cuda_runtime.h>

// Problem constants (from reference setup_inputs)
#define BD   8        // batch
#define NN   2048     // N = O*K
#define HH   128      // hidden
#define TT   10       // pred_len
#define MAXN 256      // neighbor cap (avg degree ~10)
#define TRR  32       // tile rows (all step kernels) -> grid 512

// ---------------- device scratch (no allocations allowed) ----------------
__device__ float g_pos[BD * NN * 3];
__device__ float g_vel[BD * NN * 3];
__device__ __align__(16) float g_ha[BD * NN * HH];     // h ping
__device__ __align__(16) float g_hb[BD * NN * HH];     // h pong
__device__ int   g_nbr[BD * NN * MAXN];
__device__ int   g_cnt[BD * NN];
__device__ float g_dinv[BD * NN];

// ---------------- init: pos=points, vel=0, write t=0 output ----------------
__global__ void k_init(const float* __restrict__ pts, float* __restrict__ out) {
    int id = blockIdx.x * blockDim.x + threadIdx.x;   // over B*N*3
    if (id < BD * NN * 3) {
        float v = pts[id];
        g_pos[id] = v;
        g_vel[id] = 0.f;
        int c = id % 3;
        int n = (id / 3) % NN;
        int b = id / (3 * NN);
        out[((size_t)(b * (TT + 1)) * NN + n) * 3 + c] = v;
    }
}

// ---------------- adjacency + fused layer0 h (32-row tiles) -----------------
// grid (NN/TRR, BD), 256 threads; warp owns 4 rows.
__global__ __launch_bounds__(256) void k_adj(const float* __restrict__ padding,
                                             const float* __restrict__ W0) {
    __shared__ float px[NN], py[NN], pz[NN], pd[NN];
    __shared__ float W0s[6 * HH];
    __shared__ float sv[TRR][3];
    __shared__ float sdinv[TRR];
    int b = blockIdx.y, bN = b * NN;
    int i0 = blockIdx.x * TRR;
    int tid = threadIdx.x;
    const float* pos = g_pos + (size_t)bN * 3;
    for (int j = tid; j < NN; j += 256) {
        px[j] = pos[j * 3 + 0];
        py[j] = pos[j * 3 + 1];
        pz[j] = pos[j * 3 + 2];
        pd[j] = padding[bN + j];
    }
    for (int k = tid; k < 6 * HH; k += 256) W0s[k] = W0[k];
    if (tid < TRR * 3) sv[tid / 3][tid % 3] = g_vel[(bN + i0 + tid / 3) * 3 + tid % 3];
    __syncthreads();

    int warp = tid >> 5, lane = tid & 31;
    const float R2 = 0.01f;   // float32(0.1*0.1), fp32 compare like the ref
    for (int r = 0; r < 4; r++) {
        int rr = warp * 4 + r;            // row-in-block 0..31
        int i = i0 + rr;
        float xi = px[i], yi = py[i], zi = pz[i];
        bool oki = pd[i] > 0.f;
        int base = (bN + i) * MAXN;
        int cnt = 0;
        #pragma unroll 4
        for (int t = 0; t < NN / 32; t++) {
            int j = t * 32 + lane;
            // separate mul/add rounding — matches XLA's sub/mul/reduce-add
            float dx = __fadd_rn(px[j], -xi);
            float dy = __fadd_rn(py[j], -yi);
            float dz = __fadd_rn(pz[j], -zi);
            float d2 = __fadd_rn(__fadd_rn(__fmul_rn(dx, dx), __fmul_rn(dy, dy)),
                                 __fmul_rn(dz, dz));
            // a_hat = adj + I: diagonal always 1; self at its sorted position
            bool hit = (j == i) || (oki && (pd[j] > 0.f) && (d2 < R2));
            unsigned m = __ballot_sync(0xffffffffu, hit);
            if (hit) {
                int off = cnt + __popc(m & ((1u << lane) - 1u));
                if (off < MAXN) g_nbr[base + off] = j;
            }
            cnt += __popc(m);
        }
        if (cnt > MAXN) cnt = MAXN;
        if (lane == 0) {
            // XLA lowers rsqrt as 1/sqrt (correctly rounded), NOT MUFU.RSQ.
            float di = 1.0f / sqrtf((float)cnt);
            g_cnt[bN + i]  = cnt;
            g_dinv[bN + i] = di;
            sdinv[rr] = di;
        }
    }
    __syncthreads();

    // layer0 h for own rows (ascending-k FMA, pos then vel)
    for (int o = tid; o < TRR * HH; o += 256) {
        int r = o >> 7, col = o & 127;
        float acc = 0.f;
        acc = fmaf(px[i0 + r], W0s[0 * HH + col], acc);
        acc = fmaf(py[i0 + r], W0s[1 * HH + col], acc);
        acc = fmaf(pz[i0 + r], W0s[2 * HH + col], acc);
        acc = fmaf(sv[r][0],   W0s[3 * HH + col], acc);
        acc = fmaf(sv[r][1],   W0s[4 * HH + col], acc);
        acc = fmaf(sv[r][2],   W0s[5 * HH + col], acc);
        g_ha[(size_t)(bN + i0 + r) * HH + col] = __fmul_rn(acc, sdinv[r]);
    }
}

// MLP-4 gather: 4 independent LDG.128 in flight, then ordered adds
// (strictly ascending t — bit-identical to the serial loop).
__device__ __forceinline__ float4 gather_row(const float* __restrict__ hin,
                                             const int* __restrict__ nb,
                                             int cnt, int bN, int lane) {
    float4 a = make_float4(0.f, 0.f, 0.f, 0.f);
    int t = 0;
    for (; t + 4 <= cnt; t += 4) {
        int j0 = nb[t], j1 = nb[t + 1], j2 = nb[t + 2], j3 = nb[t + 3];
        float4 v0 = __ldg((const float4*)(hin + (size_t)(bN + j0) * HH) + lane);
        float4 v1 = __ldg((const float4*)(hin + (size_t)(bN + j1) * HH) + lane);
        float4 v2 = __ldg((const float4*)(hin + (size_t)(bN + j2) * HH) + lane);
        float4 v3 = __ldg((const float4*)(hin + (size_t)(bN + j3) * HH) + lane);
        a.x = __fadd_rn(a.x, v0.x); a.y = __fadd_rn(a.y, v0.y);
        a.z = __fadd_rn(a.z, v0.z); a.w = __fadd_rn(a.w, v0.w);
        a.x = __fadd_rn(a.x, v1.x); a.y = __fadd_rn(a.y, v1.y);
        a.z = __fadd_rn(a.z, v1.z); a.w = __fadd_rn(a.w, v1.w);
        a.x = __fadd_rn(a.x, v2.x); a.y = __fadd_rn(a.y, v2.y);
        a.z = __fadd_rn(a.z, v2.z); a.w = __fadd_rn(a.w, v2.w);
        a.x = __fadd_rn(a.x, v3.x); a.y = __fadd_rn(a.y, v3.y);
        a.z = __fadd_rn(a.z, v3.z); a.w = __fadd_rn(a.w, v3.w);
    }
    for (; t < cnt; t++) {
        float4 v = __ldg((const float4*)(hin + (size_t)(bN + nb[t]) * HH) + lane);
        a.x = __fadd_rn(a.x, v.x); a.y = __fadd_rn(a.y, v.y);
        a.z = __fadd_rn(a.z, v.z); a.w = __fadd_rn(a.w, v.w);
    }
    return a;
}

// ---------------- fused aggregate + dense GEMM (32-row, 2-stage W) ----------
// Phase A: warp owns 4 rows; gather -> xs.
// Phase B: GEMM in two k-chunks of 64, W chunk streamed through 32KB smem.
// Each accumulator sees k strictly ascending -> bit-identical to monolithic.
// smem ~49.4KB -> 3 CTAs/SM. grid (BD*NN/TRR)=512.
// src==0: g_ha -> g_hb ; src==1: g_hb -> g_ha.
__global__ __launch_bounds__(256, 3) void k_aggemm(int src,
                                                   const float* __restrict__ bias,
                                                   const float* __restrict__ W) {
    extern __shared__ __align__(16) float sm[];
    float* Wc = sm;                  // 64*128 (one k-chunk)
    float* xs = sm + 64 * HH;        // 32*132 (float4-aligned pitch)
    float* dj = xs + TRR * 132;      // 32
    float* bs = dj + TRR;            // 128

    const float* hin  = src ? g_hb : g_ha;
    float*       hout = src ? g_ha : g_hb;

    int row0 = blockIdx.x * TRR;
    int tid = threadIdx.x;
    int bN = (row0 / NN) * NN;       // neighbors are batch-local ids

    // stage 0 load: W k-chunk 0 (k=0..63)
    for (int k = tid; k < 64 * HH; k += 256) Wc[k] = W[k];
    if (tid < HH) bs[tid] = bias[tid];
    if (tid < TRR) dj[tid] = g_dinv[row0 + tid];
    __syncwarp();   // bs visible to own warp's gather epilogue via syncthreads below anyway

    // Phase A: warp owns rows 4w..4w+3; gather into xs.
    int warp = tid >> 5, lane = tid & 31;
    for (int r = 0; r < 4; r++) {
        int rr = warp * 4 + r;
        int i = row0 + rr;
        float4 a = gather_row(hin, g_nbr + (size_t)i * MAXN, g_cnt[i], bN, lane);
        float di = g_dinv[i];
        float4 bb = make_float4(bias[lane * 4], bias[lane * 4 + 1],
                                bias[lane * 4 + 2], bias[lane * 4 + 3]);
        float4 o;
        o.x = fmaxf(__fadd_rn(__fmul_rn(a.x, di), bb.x), 0.f);
        o.y = fmaxf(__fadd_rn(__fmul_rn(a.y, di), bb.y), 0.f);
        o.z = fmaxf(__fadd_rn(__fmul_rn(a.z, di), bb.z), 0.f);
        o.w = fmaxf(__fadd_rn(__fmul_rn(a.w, di), bb.w), 0.f);
        *(float4*)&xs[rr * 132 + lane * 4] = o;
    }
    __syncthreads();                 // xs + Wc chunk0 ready

    // Phase B: thread (tr=warp, tc) -> rows 4*tr..+3, cols 4*tc..+3.
    int tc = tid & 31, tr = tid >> 5;
    const float* y = xs + (4 * tr) * 132;
    float acc[4][4];
    #pragma unroll
    for (int m = 0; m < 4; m++)
        #pragma unroll
        for (int n = 0; n < 4; n++) acc[m][n] = 0.f;

    #pragma unroll 4
    for (int k = 0; k < 64; k++) {
        float4 w = *(const float4*)&Wc[k * HH + 4 * tc];
        float y0 = y[k], y1 = y[132 + k], y2 = y[264 + k], y3 = y[396 + k];
        acc[0][0] = fmaf(y0, w.x, acc[0][0]); acc[0][1] = fmaf(y0, w.y, acc[0][1]);
        acc[0][2] = fmaf(y0, w.z, acc[0][2]); acc[0][3] = fmaf(y0, w.w, acc[0][3]);
        acc[1][0] = fmaf(y1, w.x, acc[1][0]); acc[1][1] = fmaf(y1, w.y, acc[1][1]);
        acc[1][2] = fmaf(y1, w.z, acc[1][2]); acc[1][3] = fmaf(y1, w.w, acc[1][3]);
        acc[2][0] = fmaf(y2, w.x, acc[2][0]); acc[2][1] = fmaf(y2, w.y, acc[2][1]);
        acc[2][2] = fmaf(y2, w.z, acc[2][2]); acc[2][3] = fmaf(y2, w.w, acc[2][3]);
        acc[3][0] = fmaf(y3, w.x, acc[3][0]); acc[3][1] = fmaf(y3, w.y, acc[3][1]);
        acc[3][2] = fmaf(y3, w.z, acc[3][2]); acc[3][3] = fmaf(y3, w.w, acc[3][3]);
    }
    __syncthreads();                 // all chunk0 reads done

    // stage 1 load: W k-chunk 1 (k=64..127)
    for (int k = tid; k < 64 * HH; k += 256) Wc[k] = W[64 * HH + k];
    __syncthreads();

    #pragma unroll 4
    for (int k = 0; k < 64; k++) {
        float4 w = *(const float4*)&Wc[k * HH + 4 * tc];
        int kk = 64 + k;
        float y0 = y[kk], y1 = y[132 + kk], y2 = y[264 + kk], y3 = y[396 + kk];
        acc[0][0] = fmaf(y0, w.x, acc[0][0]); acc[0][1] = fmaf(y0, w.y, acc[0][1]);
        acc[0][2] = fmaf(y0, w.z, acc[0][2]); acc[0][3] = fmaf(y0, w.w, acc[0][3]);
        acc[1][0] = fmaf(y1, w.x, acc[1][0]); acc[1][1] = fmaf(y1, w.y, acc[1][1]);
        acc[1][2] = fmaf(y1, w.z, acc[1][2]); acc[1][3] = fmaf(y1, w.w, acc[1][3]);
        acc[2][0] = fmaf(y2, w.x, acc[2][0]); acc[2][1] = fmaf(y2, w.y, acc[2][1]);
        acc[2][2] = fmaf(y2, w.z, acc[2][2]); acc[2][3] = fmaf(y2, w.w, acc[2][3]);
        acc[3][0] = fmaf(y3, w.x, acc[3][0]); acc[3][1] = fmaf(y3, w.y, acc[3][1]);
        acc[3][2] = fmaf(y3, w.z, acc[3][2]); acc[3][3] = fmaf(y3, w.w, acc[3][3]);
    }

    #pragma unroll
    for (int m = 0; m < 4; m++) {
        int r = 4 * tr + m;
        float d = dj[r];
        float4 o;
        o.x = __fmul_rn(acc[m][0], d);
        o.y = __fmul_rn(acc[m][1], d);
        o.z = __fmul_rn(acc[m][2], d);
        o.w = __fmul_rn(acc[m][3], d);
        *(float4*)&hout[(size_t)(row0 + r) * HH + 4 * tc] = o;
    }
}

// ---------------- fused aggregate + fc head + state update (32-row) --------
// Reads g_ha (layer2 gemm output lands there). grid 512.
__global__ __launch_bounds__(256) void k_aggfc(const float* __restrict__ bias2,
                                               const float* __restrict__ Wfc,
                                               const float* __restrict__ bfc,
                                               const float* __restrict__ padding,
                                               float* __restrict__ out, int t) {
    __shared__ __align__(16) float xs[TRR * 132];
    __shared__ float Wf[HH * 6];
    __shared__ float bf[6];
    __shared__ __align__(16) float bs[HH];
    int row0 = blockIdx.x * TRR;
    int tid = threadIdx.x;
    int bN = (row0 / NN) * NN;

    for (int k = tid; k < HH * 6; k += 256) Wf[k] = Wfc[k];
    if (tid < 6) bf[tid] = bfc[tid];
    if (tid < HH) bs[tid] = bias2[tid];
    __syncthreads();

    int warp = tid >> 5, lane = tid & 31;
    for (int r = 0; r < 4; r++) {
        int rr = warp * 4 + r;
        int i = row0 + rr;
        float4 a = gather_row(g_ha, g_nbr + (size_t)i * MAXN, g_cnt[i], bN, lane);
        float di = g_dinv[i];
        float4 bb = ((const float4*)bs)[lane];
        float4 o;
        o.x = fmaxf(__fadd_rn(__fmul_rn(a.x, di), bb.x), 0.f);
        o.y = fmaxf(__fadd_rn(__fmul_rn(a.y, di), bb.y), 0.f);
        o.z = fmaxf(__fadd_rn(__fmul_rn(a.z, di), bb.z), 0.f);
        o.w = fmaxf(__fadd_rn(__fmul_rn(a.w, di), bb.w), 0.f);
        *(float4*)&xs[rr * 132 + lane * 4] = o;
    }
    __syncthreads();

    // fc: 32 rows x 6 outputs = 192 threads
    if (tid < TRR * 6) {
        int r = tid / 6, c = tid % 6;
        int g = row0 + r;
        const float* xr = xs + r * 132;
        float acc = 0.f;
        #pragma unroll 8
        for (int k = 0; k < HH; k++) acc = fmaf(xr[k], Wf[k * 6 + c], acc);
        float res = __fadd_rn(acc, bf[c]);
        res = __fmul_rn(res, padding[g]);
        if (c < 3) {
            float p = __fadd_rn(g_pos[g * 3 + c], res);
            g_pos[g * 3 + c] = p;
            int b = g / NN, n = g % NN;
            out[((size_t)(b * (TT + 1) + t + 1) * NN + n) * 3 + c] = p;
        } else {
            int a = g * 3 + (c - 3);
            g_vel[a] = __fadd_rn(g_vel[a], res);
        }
    }
}

// ---------------- launch ----------------
extern "C" void kernel_launch(void* const* d_in, const int* in_sizes, int n_in,
                              void* d_out, int out_size) {
    const float* points  = (const float*)d_in[0];
    const float* padding = (const float*)d_in[5];
    const float* W0  = (const float*)d_in[6];
    const float* b0  = (const float*)d_in[7];
    const float* W1  = (const float*)d_in[8];
    const float* b1  = (const float*)d_in[9];
    const float* W2  = (const float*)d_in[10];
    const float* b2  = (const float*)d_in[11];
    const float* Wfc = (const float*)d_in[12];
    const float* bfc = (const float*)d_in[13];
    float* out = (float*)d_out;

    const int smem_ag = (64 * HH + TRR * 132 + TRR + HH) * (int)sizeof(float);
    cudaFuncSetAttribute(k_aggemm, cudaFuncAttributeMaxDynamicSharedMemorySize,
                         smem_ag);

    const int ROWS = BD * NN;

    k_init<<<(BD * NN * 3 + 255) / 256, 256>>>(points, out);

    for (int t = 0; t < TT; t++) {
        k_adj<<<dim3(NN / TRR, BD), 256>>>(padding, W0);       // -> g_ha (h0)
        k_aggemm<<<ROWS / TRR, 256, smem_ag>>>(0, b0, W1);     // ha -> x -> hb
        k_aggemm<<<ROWS / TRR, 256, smem_ag>>>(1, b1, W2);     // hb -> x -> ha
        k_aggfc <<<ROWS / TRR, 256>>>(b2, Wfc, bfc, padding, out, t);
    }
}

// round 14
// speedup vs baseline: 1.4245x; 1.2231x over previous
#include <cuda_runtime.h>

// Problem constants (from reference setup_inputs)
#define BD   8        // batch
#define NN   2048     // N = O*K
#define HH   128      // hidden
#define TT   10       // pred_len
#define MAXN 256      // neighbor cap (avg degree ~10)

// ---------------- device scratch (no allocations allowed) ----------------
__device__ float g_pos[BD * NN * 3];
__device__ float g_vel[BD * NN * 3];
__device__ __align__(16) float g_ha[BD * NN * HH];     // h ping
__device__ __align__(16) float g_hb[BD * NN * HH];     // h pong
__device__ int   g_nbr[BD * NN * MAXN];
__device__ int   g_cnt[BD * NN];
__device__ float g_dinv[BD * NN];

// ---------------- init: pos=points, vel=0, write t=0 output ----------------
__global__ void k_init(const float* __restrict__ pts, float* __restrict__ out) {
    int id = blockIdx.x * blockDim.x + threadIdx.x;   // over B*N*3
    if (id < BD * NN * 3) {
        float v = pts[id];
        g_pos[id] = v;
        g_vel[id] = 0.f;
        int c = id % 3;
        int n = (id / 3) % NN;
        int b = id / (3 * NN);
        out[((size_t)(b * (TT + 1)) * NN + n) * 3 + c] = v;
    }
}

// ---------------- adjacency + fused layer0 h (64-row tiles, 512 thr) --------
// grid (NN/64, BD); 16 warps, warp owns 4 rows.
__global__ __launch_bounds__(512) void k_adj(const float* __restrict__ padding,
                                             const float* __restrict__ W0) {
    __shared__ float px[NN], py[NN], pz[NN], pd[NN];
    __shared__ float W0s[6 * HH];
    __shared__ float sv[64][3];
    __shared__ float sdinv[64];
    int b = blockIdx.y, bN = b * NN;
    int i0 = blockIdx.x * 64;
    int tid = threadIdx.x;
    const float* pos = g_pos + (size_t)bN * 3;
    for (int j = tid; j < NN; j += 512) {
        px[j] = pos[j * 3 + 0];
        py[j] = pos[j * 3 + 1];
        pz[j] = pos[j * 3 + 2];
        pd[j] = padding[bN + j];
    }
    for (int k = tid; k < 6 * HH; k += 512) W0s[k] = W0[k];
    if (tid < 192) sv[tid / 3][tid % 3] = g_vel[(bN + i0 + tid / 3) * 3 + tid % 3];
    __syncthreads();

    int warp = tid >> 5, lane = tid & 31;
    const float R2 = 0.01f;   // float32(0.1*0.1), fp32 compare like the ref
    for (int r = 0; r < 4; r++) {
        int rr = warp * 4 + r;            // row-in-block 0..63
        int i = i0 + rr;
        float xi = px[i], yi = py[i], zi = pz[i];
        bool oki = pd[i] > 0.f;
        int base = (bN + i) * MAXN;
        int cnt = 0;
        #pragma unroll 4
        for (int t = 0; t < NN / 32; t++) {
            int j = t * 32 + lane;
            // separate mul/add rounding — matches XLA's sub/mul/reduce-add
            float dx = __fadd_rn(px[j], -xi);
            float dy = __fadd_rn(py[j], -yi);
            float dz = __fadd_rn(pz[j], -zi);
            float d2 = __fadd_rn(__fadd_rn(__fmul_rn(dx, dx), __fmul_rn(dy, dy)),
                                 __fmul_rn(dz, dz));
            // a_hat = adj + I: diagonal always 1; self at its sorted position
            bool hit = (j == i) || (oki && (pd[j] > 0.f) && (d2 < R2));
            unsigned m = __ballot_sync(0xffffffffu, hit);
            if (hit) {
                int off = cnt + __popc(m & ((1u << lane) - 1u));
                if (off < MAXN) g_nbr[base + off] = j;
            }
            cnt += __popc(m);
        }
        if (cnt > MAXN) cnt = MAXN;
        if (lane == 0) {
            // XLA lowers rsqrt as 1/sqrt (correctly rounded), NOT MUFU.RSQ.
            float di = 1.0f / sqrtf((float)cnt);
            g_cnt[bN + i]  = cnt;
            g_dinv[bN + i] = di;
            sdinv[rr] = di;
        }
    }
    __syncthreads();

    // layer0 h for own rows (ascending-k FMA, pos then vel)
    for (int o = tid; o < 64 * HH; o += 512) {
        int r = o >> 7, col = o & 127;
        float acc = 0.f;
        acc = fmaf(px[i0 + r], W0s[0 * HH + col], acc);
        acc = fmaf(py[i0 + r], W0s[1 * HH + col], acc);
        acc = fmaf(pz[i0 + r], W0s[2 * HH + col], acc);
        acc = fmaf(sv[r][0],   W0s[3 * HH + col], acc);
        acc = fmaf(sv[r][1],   W0s[4 * HH + col], acc);
        acc = fmaf(sv[r][2],   W0s[5 * HH + col], acc);
        g_ha[(size_t)(bN + i0 + r) * HH + col] = __fmul_rn(acc, sdinv[r]);
    }
}

// MLP-4 gather: 4 independent LDG.128 in flight, then ordered adds
// (strictly ascending t — bit-identical to the serial loop).
__device__ __forceinline__ float4 gather_row(const float* __restrict__ hin,
                                             const int* __restrict__ nb,
                                             int cnt, int bN, int lane) {
    float4 a = make_float4(0.f, 0.f, 0.f, 0.f);
    int t = 0;
    for (; t + 4 <= cnt; t += 4) {
        int j0 = nb[t], j1 = nb[t + 1], j2 = nb[t + 2], j3 = nb[t + 3];
        float4 v0 = __ldg((const float4*)(hin + (size_t)(bN + j0) * HH) + lane);
        float4 v1 = __ldg((const float4*)(hin + (size_t)(bN + j1) * HH) + lane);
        float4 v2 = __ldg((const float4*)(hin + (size_t)(bN + j2) * HH) + lane);
        float4 v3 = __ldg((const float4*)(hin + (size_t)(bN + j3) * HH) + lane);
        a.x = __fadd_rn(a.x, v0.x); a.y = __fadd_rn(a.y, v0.y);
        a.z = __fadd_rn(a.z, v0.z); a.w = __fadd_rn(a.w, v0.w);
        a.x = __fadd_rn(a.x, v1.x); a.y = __fadd_rn(a.y, v1.y);
        a.z = __fadd_rn(a.z, v1.z); a.w = __fadd_rn(a.w, v1.w);
        a.x = __fadd_rn(a.x, v2.x); a.y = __fadd_rn(a.y, v2.y);
        a.z = __fadd_rn(a.z, v2.z); a.w = __fadd_rn(a.w, v2.w);
        a.x = __fadd_rn(a.x, v3.x); a.y = __fadd_rn(a.y, v3.y);
        a.z = __fadd_rn(a.z, v3.z); a.w = __fadd_rn(a.w, v3.w);
    }
    for (; t < cnt; t++) {
        float4 v = __ldg((const float4*)(hin + (size_t)(bN + nb[t]) * HH) + lane);
        a.x = __fadd_rn(a.x, v.x); a.y = __fadd_rn(a.y, v.y);
        a.z = __fadd_rn(a.z, v.z); a.w = __fadd_rn(a.w, v.w);
    }
    return a;
}

// ---------------- fused aggregate + dense GEMM, warp-local, 512 thr ---------
// 64-row tile, grid 256 (single wave). Warp w owns rows 4w..4w+3:
// gather -> xs, __syncwarp, GEMM own rows (4 rows x 4 cols per thread).
// Full W in smem; only one block sync (after W/bias load).
// src==0: g_ha -> g_hb ; src==1: g_hb -> g_ha.
__global__ __launch_bounds__(512, 2) void k_aggemm(int src,
                                                   const float* __restrict__ bias,
                                                   const float* __restrict__ W) {
    extern __shared__ __align__(16) float sm[];
    float* Ws = sm;                  // 128*128
    float* xs = sm + HH * HH;        // 64*132 (float4-aligned pitch)
    float* dj = xs + 64 * 132;       // 64
    float* bs = dj + 64;             // 128

    const float* hin  = src ? g_hb : g_ha;
    float*       hout = src ? g_ha : g_hb;

    int row0 = blockIdx.x * 64;
    int tid = threadIdx.x;
    int bN = (row0 / NN) * NN;       // neighbors are batch-local ids

    for (int k = tid; k < HH * HH; k += 512) Ws[k] = W[k];
    if (tid < HH) bs[tid] = bias[tid];
    if (tid < 64) dj[tid] = g_dinv[row0 + tid];
    __syncthreads();                 // only block sync

    int warp = tid >> 5, lane = tid & 31;
    int rbase = warp * 4;

    // Phase A (warp-local): gather own 4 rows into xs
    float4 bb = ((const float4*)bs)[lane];
    #pragma unroll 1
    for (int rr = 0; rr < 4; rr++) {
        int r = rbase + rr;
        int i = row0 + r;
        float4 a = gather_row(hin, g_nbr + (size_t)i * MAXN, g_cnt[i], bN, lane);
        float di = dj[r];
        float4 o;
        o.x = fmaxf(__fadd_rn(__fmul_rn(a.x, di), bb.x), 0.f);
        o.y = fmaxf(__fadd_rn(__fmul_rn(a.y, di), bb.y), 0.f);
        o.z = fmaxf(__fadd_rn(__fmul_rn(a.z, di), bb.z), 0.f);
        o.w = fmaxf(__fadd_rn(__fmul_rn(a.w, di), bb.w), 0.f);
        *(float4*)&xs[r * 132 + lane * 4] = o;
    }
    __syncwarp();                    // xs warp-local ordering

    // Phase B (warp-local): rows rbase..rbase+3, cols lane*4..lane*4+3.
    // k strictly ascending per accumulator — bit-identical chain.
    const float* y = xs + rbase * 132;
    float acc[4][4];
    #pragma unroll
    for (int m = 0; m < 4; m++)
        #pragma unroll
        for (int n = 0; n < 4; n++) acc[m][n] = 0.f;

    #pragma unroll 1
    for (int k0 = 0; k0 < HH; k0 += 4) {
        float4 yv0 = *(const float4*)&y[k0];
        float4 yv1 = *(const float4*)&y[132 + k0];
        float4 yv2 = *(const float4*)&y[264 + k0];
        float4 yv3 = *(const float4*)&y[396 + k0];
        #pragma unroll
        for (int kk = 0; kk < 4; kk++) {
            float4 w = *(const float4*)&Ws[(k0 + kk) * HH + lane * 4];
            float y0 = (kk == 0) ? yv0.x : (kk == 1) ? yv0.y : (kk == 2) ? yv0.z : yv0.w;
            float y1 = (kk == 0) ? yv1.x : (kk == 1) ? yv1.y : (kk == 2) ? yv1.z : yv1.w;
            float y2 = (kk == 0) ? yv2.x : (kk == 1) ? yv2.y : (kk == 2) ? yv2.z : yv2.w;
            float y3 = (kk == 0) ? yv3.x : (kk == 1) ? yv3.y : (kk == 2) ? yv3.z : yv3.w;
            acc[0][0] = fmaf(y0, w.x, acc[0][0]); acc[0][1] = fmaf(y0, w.y, acc[0][1]);
            acc[0][2] = fmaf(y0, w.z, acc[0][2]); acc[0][3] = fmaf(y0, w.w, acc[0][3]);
            acc[1][0] = fmaf(y1, w.x, acc[1][0]); acc[1][1] = fmaf(y1, w.y, acc[1][1]);
            acc[1][2] = fmaf(y1, w.z, acc[1][2]); acc[1][3] = fmaf(y1, w.w, acc[1][3]);
            acc[2][0] = fmaf(y2, w.x, acc[2][0]); acc[2][1] = fmaf(y2, w.y, acc[2][1]);
            acc[2][2] = fmaf(y2, w.z, acc[2][2]); acc[2][3] = fmaf(y2, w.w, acc[2][3]);
            acc[3][0] = fmaf(y3, w.x, acc[3][0]); acc[3][1] = fmaf(y3, w.y, acc[3][1]);
            acc[3][2] = fmaf(y3, w.z, acc[3][2]); acc[3][3] = fmaf(y3, w.w, acc[3][3]);
        }
    }

    #pragma unroll
    for (int m = 0; m < 4; m++) {
        int r = rbase + m;
        float d = dj[r];
        float4 o;
        o.x = __fmul_rn(acc[m][0], d);
        o.y = __fmul_rn(acc[m][1], d);
        o.z = __fmul_rn(acc[m][2], d);
        o.w = __fmul_rn(acc[m][3], d);
        *(float4*)&hout[(size_t)(row0 + r) * HH + lane * 4] = o;
    }
}

// ---------------- fused aggregate + fc head + state update, warp-local -----
// 64-row tiles, 512 threads, warp owns 4 rows. Reads g_ha.
__global__ __launch_bounds__(512) void k_aggfc(const float* __restrict__ bias2,
                                               const float* __restrict__ Wfc,
                                               const float* __restrict__ bfc,
                                               const float* __restrict__ padding,
                                               float* __restrict__ out, int t) {
    __shared__ __align__(16) float xs[64 * 132];
    __shared__ float Wf[HH * 6];
    __shared__ float bf[6];
    __shared__ __align__(16) float bs[HH];
    int row0 = blockIdx.x * 64;
    int tid = threadIdx.x;
    int bN = (row0 / NN) * NN;

    for (int k = tid; k < HH * 6; k += 512) Wf[k] = Wfc[k];
    if (tid < 6) bf[tid] = bfc[tid];
    if (tid < HH) bs[tid] = bias2[tid];
    __syncthreads();

    int warp = tid >> 5, lane = tid & 31;
    int rbase = warp * 4;
    #pragma unroll 1
    for (int rr = 0; rr < 4; rr++) {
        int r = rbase + rr;
        int i = row0 + r;
        float4 a = gather_row(g_ha, g_nbr + (size_t)i * MAXN, g_cnt[i], bN, lane);
        float di = g_dinv[i];
        float4 bb = ((const float4*)bs)[lane];
        float4 o;
        o.x = fmaxf(__fadd_rn(__fmul_rn(a.x, di), bb.x), 0.f);
        o.y = fmaxf(__fadd_rn(__fmul_rn(a.y, di), bb.y), 0.f);
        o.z = fmaxf(__fadd_rn(__fmul_rn(a.z, di), bb.z), 0.f);
        o.w = fmaxf(__fadd_rn(__fmul_rn(a.w, di), bb.w), 0.f);
        *(float4*)&xs[r * 132 + lane * 4] = o;
    }
    __syncwarp();

    // fc for own 4 rows: 24 outputs per warp (lanes 0..23).
    if (lane < 24) {
        int rr = lane / 6, c = lane % 6;
        int g = row0 + rbase + rr;
        const float* xr = xs + (rbase + rr) * 132;
        float acc = 0.f;
        #pragma unroll 8
        for (int k = 0; k < HH; k++) acc = fmaf(xr[k], Wf[k * 6 + c], acc);
        float res = __fadd_rn(acc, bf[c]);
        res = __fmul_rn(res, padding[g]);
        if (c < 3) {
            float p = __fadd_rn(g_pos[g * 3 + c], res);
            g_pos[g * 3 + c] = p;
            int b = g / NN, n = g % NN;
            out[((size_t)(b * (TT + 1) + t + 1) * NN + n) * 3 + c] = p;
        } else {
            int a = g * 3 + (c - 3);
            g_vel[a] = __fadd_rn(g_vel[a], res);
        }
    }
}

// ---------------- launch ----------------
extern "C" void kernel_launch(void* const* d_in, const int* in_sizes, int n_in,
                              void* d_out, int out_size) {
    const float* points  = (const float*)d_in[0];
    const float* padding = (const float*)d_in[5];
    const float* W0  = (const float*)d_in[6];
    const float* b0  = (const float*)d_in[7];
    const float* W1  = (const float*)d_in[8];
    const float* b1  = (const float*)d_in[9];
    const float* W2  = (const float*)d_in[10];
    const float* b2  = (const float*)d_in[11];
    const float* Wfc = (const float*)d_in[12];
    const float* bfc = (const float*)d_in[13];
    float* out = (float*)d_out;

    const int smem_ag = (HH * HH + 64 * 132 + 64 + HH) * (int)sizeof(float);
    cudaFuncSetAttribute(k_aggemm, cudaFuncAttributeMaxDynamicSharedMemorySize,
                         smem_ag);

    const int ROWS = BD * NN;

    k_init<<<(BD * NN * 3 + 255) / 256, 256>>>(points, out);

    for (int t = 0; t < TT; t++) {
        k_adj<<<dim3(NN / 64, BD), 512>>>(padding, W0);      // -> g_ha (h0)
        k_aggemm<<<ROWS / 64, 512, smem_ag>>>(0, b0, W1);    // ha -> x -> hb
        k_aggemm<<<ROWS / 64, 512, smem_ag>>>(1, b1, W2);    // hb -> x -> ha
        k_aggfc <<<ROWS / 64, 512>>>(b2, Wfc, bfc, padding, out, t);
    }
}